// round 4
// baseline (speedup 1.0000x reference)
#include <cuda_runtime.h>

#define D        256
#define H        16
#define ROWS     128
#define THREADS  256
#define RP       129   // xs row stride (odd -> conflict-free transpose stores)
#define W2TS     20    // transposed-W2 row stride (16B-aligned, 16 payload floats)
#define HBS      18    // h-partial buffer row stride (even -> 8B-aligned u64 ops)

typedef unsigned long long u64;

static __device__ __forceinline__ u64 pack2(float a, float b) {
    u64 r; asm("mov.b64 %0, {%1, %2};" : "=l"(r) : "f"(a), "f"(b)); return r;
}
static __device__ __forceinline__ void unpack2(u64 v, float& a, float& b) {
    asm("mov.b64 {%0, %1}, %2;" : "=f"(a), "=f"(b) : "l"(v));
}
static __device__ __forceinline__ u64 fma2(u64 a, u64 b, u64 c) {
    u64 d; asm("fma.rn.f32x2 %0, %1, %2, %3;" : "=l"(d) : "l"(a), "l"(b), "l"(c)); return d;
}
static __device__ __forceinline__ float ex2f(float x) {
    float r; asm("ex2.approx.f32 %0, %1;" : "=f"(r) : "f"(x)); return r;
}
static __device__ __forceinline__ float rcpf(float x) {
    float r; asm("rcp.approx.f32 %0, %1;" : "=f"(r) : "f"(x)); return r;
}

__global__ __launch_bounds__(THREADS, 1)
void fb_kernel(const float* __restrict__ x, const float* __restrict__ W1,
               const float* __restrict__ W2, float* __restrict__ out, int n)
{
    extern __shared__ float smem[];
    float* xs  = smem;                 // [256][129] transposed x tile
    float* W1s = smem + D * RP;        // [256][16]  (k-major, matches input)
    float* W2t = W1s + D * H;          // [256][20]  W2 transposed to k-major
    float* hb  = W2t + D * W2TS;       // [2][128][18] split-K h partials

    const int t     = threadIdx.x;
    const int r     = t & (ROWS - 1);
    const int half  = t >> 7;
    const int kbase = half * (D / 2);
    const int row0  = blockIdx.x * ROWS;
    const int nrows = min(ROWS, n - row0);

    // ---- stage weights ----
    for (int i = t; i < D * H; i += THREADS) W1s[i] = W1[i];
    for (int i = t; i < H * D; i += THREADS) {
        int j = i >> 8, k = i & (D - 1);
        W2t[k * W2TS + j] = W2[i];
    }
    // ---- stage x tile, transposed (coalesced LDG, conflict-free STS) ----
    for (int p = t; p < nrows * D; p += THREADS) {
        int rr = p >> 8, k = p & (D - 1);
        xs[k * RP + rr] = x[(long long)(row0 + rr) * D + k];
    }
    __syncthreads();

    // ---- pass 1: partial h = x[:, kbase:kbase+128] @ W1[kbase:kbase+128, :]
    u64 acc[8];
    #pragma unroll
    for (int i = 0; i < 8; i++) acc[i] = pack2(0.f, 0.f);
    #pragma unroll 4
    for (int kk = 0; kk < D / 2; kk++) {
        int k = kbase + kk;
        float xv = xs[k * RP + r];
        u64 xx = pack2(xv, xv);
        const ulonglong2* wr = reinterpret_cast<const ulonglong2*>(W1s + k * H);
        ulonglong2 wa = wr[0], wb = wr[1];
        acc[0] = fma2(xx, wa.x, acc[0]);
        acc[1] = fma2(xx, wa.y, acc[1]);
        acc[2] = fma2(xx, wb.x, acc[2]);
        acc[3] = fma2(xx, wb.y, acc[3]);
        ulonglong2 wc = wr[2], wd = wr[3];
        acc[4] = fma2(xx, wc.x, acc[4]);
        acc[5] = fma2(xx, wc.y, acc[5]);
        acc[6] = fma2(xx, wd.x, acc[6]);
        acc[7] = fma2(xx, wd.y, acc[7]);
    }
    // publish partials
    {
        u64* dst = reinterpret_cast<u64*>(hb + (half * ROWS + r) * HBS);
        #pragma unroll
        for (int i = 0; i < 8; i++) dst[i] = acc[i];
    }
    __syncthreads();

    // ---- combine halves, ReLU, pack h pairs ----
    u64 hp[8];
    {
        const u64* src = reinterpret_cast<const u64*>(hb + ((1 - half) * ROWS + r) * HBS);
        #pragma unroll
        for (int i = 0; i < 8; i++) {
            float a0, a1, b0, b1;
            unpack2(acc[i], a0, a1);
            unpack2(src[i], b0, b1);
            hp[i] = pack2(fmaxf(a0 + b0, 0.f), fmaxf(a1 + b1, 0.f));
        }
    }

    // ---- pass 2: s = h @ W2[:, k]; gate; write result back into xs ----
    #pragma unroll 4
    for (int kk = 0; kk < D / 2; kk++) {
        int k = kbase + kk;
        const ulonglong2* wr = reinterpret_cast<const ulonglong2*>(W2t + k * W2TS);
        ulonglong2 wa = wr[0], wb = wr[1];
        u64 a = pack2(0.f, 0.f);
        u64 b = pack2(0.f, 0.f);
        a = fma2(hp[0], wa.x, a);
        b = fma2(hp[1], wa.y, b);
        a = fma2(hp[2], wb.x, a);
        b = fma2(hp[3], wb.y, b);
        ulonglong2 wc = wr[2], wd = wr[3];
        a = fma2(hp[4], wc.x, a);
        b = fma2(hp[5], wc.y, b);
        a = fma2(hp[6], wd.x, a);
        b = fma2(hp[7], wd.y, b);
        float a0, a1, b0, b1;
        unpack2(a, a0, a1);
        unpack2(b, b0, b1);
        float s = (a0 + b0) + (a1 + b1);
        // sigmoid(2s) = 1 / (1 + 2^(-2s*log2(e)))
        float e = ex2f(s * -2.8853900817779268f);
        float y = rcpf(1.0f + e);
        xs[k * RP + r] *= y;
    }
    __syncthreads();

    // ---- stream results out (conflict-free LDS, coalesced STG) ----
    for (int p = t; p < nrows * D; p += THREADS) {
        int rr = p >> 8, k = p & (D - 1);
        out[(long long)(row0 + rr) * D + k] = xs[k * RP + rr];
    }
}

extern "C" void kernel_launch(void* const* d_in, const int* in_sizes, int n_in,
                              void* d_out, int out_size) {
    const float* x  = (const float*)d_in[0];
    const float* W1 = (const float*)d_in[1];
    const float* W2 = (const float*)d_in[2];
    float* out = (float*)d_out;
    int n = in_sizes[0] / D;

    int smem_bytes = (D * RP + D * H + D * W2TS + 2 * ROWS * HBS) * (int)sizeof(float);
    cudaFuncSetAttribute(fb_kernel, cudaFuncAttributeMaxDynamicSharedMemorySize, smem_bytes);
    int grid = (n + ROWS - 1) / ROWS;
    fb_kernel<<<grid, THREADS, smem_bytes>>>(x, W1, W2, out, n);
}

// round 5
// speedup vs baseline: 2.1148x; 2.1148x over previous
#include <cuda_runtime.h>

#define D        256
#define H        16
#define ROWS     128
#define THREADS  256
#define CHUNK    16     // k-columns per half per chunk
#define NCH      8      // 128 / CHUNK chunks per half
#define JW       (2*CHUNK)
#define RP       129    // xc row stride (odd -> conflict-free)

typedef unsigned long long u64;

static __device__ __forceinline__ u64 pack2(float a, float b) {
    u64 r; asm("mov.b64 %0, {%1, %2};" : "=l"(r) : "f"(a), "f"(b)); return r;
}
static __device__ __forceinline__ void unpack2(u64 v, float& a, float& b) {
    asm("mov.b64 {%0, %1}, %2;" : "=f"(a), "=f"(b) : "l"(v));
}
static __device__ __forceinline__ u64 fma2(u64 a, u64 b, u64 c) {
    u64 d; asm("fma.rn.f32x2 %0, %1, %2, %3;" : "=l"(d) : "l"(a), "l"(b), "l"(c)); return d;
}
static __device__ __forceinline__ u64 add2(u64 a, u64 b) {
    u64 d; asm("add.rn.f32x2 %0, %1, %2;" : "=l"(d) : "l"(a), "l"(b)); return d;
}
static __device__ __forceinline__ float ex2f(float x) {
    float r; asm("ex2.approx.f32 %0, %1;" : "=f"(r) : "f"(x)); return r;
}
static __device__ __forceinline__ float rcpf(float x) {
    float r; asm("rcp.approx.f32 %0, %1;" : "=f"(r) : "f"(x)); return r;
}

// W rows stored interleaved: physical row of logical k is 2*(k&127) + (k>>7),
// so the two halves a warp touches (k and k+128) sit 64B apart -> disjoint banks.
__global__ __launch_bounds__(THREADS, 4)
void fb_kernel(const float* __restrict__ x, const float* __restrict__ W1,
               const float* __restrict__ W2, float* __restrict__ out, int n)
{
    extern __shared__ float smem[];
    float* W1p = smem;             // [256][16] interleaved rows
    float* W2p = smem + D * H;     // [256][16] interleaved rows, j-contiguous
    float* xc  = W2p + D * H;      // [32][129]  x-chunk, later reused as y-chunk

    const int t    = threadIdx.x;
    const int half = t & 1;        // split-K partner = lane^1
    const int r    = t >> 1;       // row within tile, 0..127
    const int row0 = blockIdx.x * ROWS;
    const int nrows = min(ROWS, n - row0);

    // ---- stage weights (interleaved rows) ----
    for (int i = t; i < D * H; i += THREADS) {
        int k = i >> 4, j = i & 15;
        int pr = ((k & 127) << 1) | (k >> 7);
        W1p[pr * H + j] = W1[i];
    }
    for (int i = t; i < H * D; i += THREADS) {
        int j = i >> 8, k = i & 255;
        int pr = ((k & 127) << 1) | (k >> 7);
        W2p[pr * H + j] = W2[i];
    }
    __syncthreads();

    // ================= pass 1: h = relu(x @ W1), split-K over halves =========
    u64 acc[8];
    #pragma unroll
    for (int i = 0; i < 8; i++) acc[i] = 0ULL;

    for (int c = 0; c < NCH; c++) {
        // stage chunk: k in [c*16, c*16+16) U [128+c*16, 128+c*16+16)
        #pragma unroll
        for (int it = 0; it < 4; it++) {
            int idx = t + it * THREADS;         // 0..1023
            int rr = idx >> 3, jg = idx & 7;
            int kh = jg >> 2;                   // which half
            int kl = (jg & 3) << 2;             // 0,4,8,12
            if (rr < nrows) {
                const float4 v = *reinterpret_cast<const float4*>(
                    x + (long long)(row0 + rr) * D + kh * 128 + c * CHUNK + kl);
                int j0 = 4 * jg;                // = kh*CHUNK + kl
                xc[(j0 + 0) * RP + rr] = v.x;
                xc[(j0 + 1) * RP + rr] = v.y;
                xc[(j0 + 2) * RP + rr] = v.z;
                xc[(j0 + 3) * RP + rr] = v.w;
            }
        }
        __syncthreads();

        const float* xcol  = xc + (half * CHUNK) * RP + r;
        const float* wbase = W1p + (2 * (c * CHUNK) + half) * H;
        #pragma unroll
        for (int kk = 0; kk < CHUNK; kk++) {
            float xv = xcol[kk * RP];
            u64 xx = pack2(xv, xv);
            const ulonglong2* wr = reinterpret_cast<const ulonglong2*>(wbase + kk * 2 * H);
            ulonglong2 wa = wr[0], wb = wr[1];
            acc[0] = fma2(xx, wa.x, acc[0]);
            acc[1] = fma2(xx, wa.y, acc[1]);
            acc[2] = fma2(xx, wb.x, acc[2]);
            acc[3] = fma2(xx, wb.y, acc[3]);
            ulonglong2 wc2 = wr[2], wd = wr[3];
            acc[4] = fma2(xx, wc2.x, acc[4]);
            acc[5] = fma2(xx, wc2.y, acc[5]);
            acc[6] = fma2(xx, wd.x, acc[6]);
            acc[7] = fma2(xx, wd.y, acc[7]);
        }
        __syncthreads();
    }

    // ---- combine split-K halves via adjacent-lane shuffle, ReLU ----
    u64 hp[8];
    #pragma unroll
    for (int i = 0; i < 8; i++) {
        float a0, a1;
        unpack2(acc[i], a0, a1);
        float b0 = __shfl_xor_sync(0xffffffffu, a0, 1);
        float b1 = __shfl_xor_sync(0xffffffffu, a1, 1);
        hp[i] = pack2(fmaxf(a0 + b0, 0.f), fmaxf(a1 + b1, 0.f));
    }

    // ================= pass 2: y = sigmoid(2 * h @ W2); out = x * y ==========
    for (int c = 0; c < NCH; c++) {
        float* ycol        = xc + (half * CHUNK) * RP + r;
        const float* w2b   = W2p + (2 * (c * CHUNK) + half) * H;
        #pragma unroll
        for (int kk = 0; kk < CHUNK; kk++) {
            const ulonglong2* wr = reinterpret_cast<const ulonglong2*>(w2b + kk * 2 * H);
            ulonglong2 wa = wr[0], wb = wr[1];
            u64 a = 0ULL, b = 0ULL;
            a = fma2(hp[0], wa.x, a);
            b = fma2(hp[1], wa.y, b);
            a = fma2(hp[2], wb.x, a);
            b = fma2(hp[3], wb.y, b);
            ulonglong2 wc2 = wr[2], wd = wr[3];
            a = fma2(hp[4], wc2.x, a);
            b = fma2(hp[5], wc2.y, b);
            a = fma2(hp[6], wd.x, a);
            b = fma2(hp[7], wd.y, b);
            u64 s2 = add2(a, b);
            float s0, s1;
            unpack2(s2, s0, s1);
            float s = s0 + s1;
            // sigmoid(2s) = 1 / (1 + 2^(-2s*log2 e))
            float e = ex2f(s * -2.8853900817779268f);
            ycol[kk * RP] = rcpf(1.0f + e);
        }
        __syncthreads();

        // output: re-read x (L2-hot), multiply by gate, coalesced STG.128
        #pragma unroll
        for (int it = 0; it < 4; it++) {
            int idx = t + it * THREADS;
            int rr = idx >> 3, jg = idx & 7;
            int kh = jg >> 2;
            int kl = (jg & 3) << 2;
            if (rr < nrows) {
                long long g = (long long)(row0 + rr) * D + kh * 128 + c * CHUNK + kl;
                float4 v = *reinterpret_cast<const float4*>(x + g);
                int j0 = 4 * jg;
                v.x *= xc[(j0 + 0) * RP + rr];
                v.y *= xc[(j0 + 1) * RP + rr];
                v.z *= xc[(j0 + 2) * RP + rr];
                v.w *= xc[(j0 + 3) * RP + rr];
                *reinterpret_cast<float4*>(out + g) = v;
            }
        }
        __syncthreads();
    }
}

extern "C" void kernel_launch(void* const* d_in, const int* in_sizes, int n_in,
                              void* d_out, int out_size) {
    const float* x  = (const float*)d_in[0];
    const float* W1 = (const float*)d_in[1];
    const float* W2 = (const float*)d_in[2];
    float* out = (float*)d_out;
    int n = in_sizes[0] / D;

    int smem_bytes = (2 * D * H + JW * RP) * (int)sizeof(float);  // 49280 B
    cudaFuncSetAttribute(fb_kernel, cudaFuncAttributeMaxDynamicSharedMemorySize, smem_bytes);
    int grid = (n + ROWS - 1) / ROWS;
    fb_kernel<<<grid, THREADS, smem_bytes>>>(x, W1, W2, out, n);
}

// round 6
// speedup vs baseline: 2.4428x; 1.1551x over previous
#include <cuda_runtime.h>

#define D        256
#define H        16
#define RTILE    512    // rows per block
#define THREADS  256
#define CHUNK    8      // k-columns staged per chunk
#define NCH      32     // 256/8

typedef unsigned long long u64;

static __device__ __forceinline__ u64 pack2(float a, float b) {
    u64 r; asm("mov.b64 %0, {%1, %2};" : "=l"(r) : "f"(a), "f"(b)); return r;
}
static __device__ __forceinline__ void unpack2(u64 v, float& a, float& b) {
    asm("mov.b64 {%0, %1}, %2;" : "=f"(a), "=f"(b) : "l"(v));
}
static __device__ __forceinline__ u64 fma2(u64 a, u64 b, u64 c) {
    u64 d; asm("fma.rn.f32x2 %0, %1, %2, %3;" : "=l"(d) : "l"(a), "l"(b), "l"(c)); return d;
}
static __device__ __forceinline__ float ex2f(float x) {
    float r; asm("ex2.approx.f32 %0, %1;" : "=f"(r) : "f"(x)); return r;
}
static __device__ __forceinline__ float rcpf(float x) {
    float r; asm("rcp.approx.f32 %0, %1;" : "=f"(r) : "f"(x)); return r;
}
static __device__ __forceinline__ float sigmoid2(float s) {
    // sigmoid(2s) = 1 / (1 + 2^(-2s*log2 e))
    return rcpf(1.0f + ex2f(s * -2.8853900817779268f));
}

// Shared layout (floats):
//   W1s [0, 4096)          : W1 [256][16] k-major, broadcast reads
//   hb  [4096, 12288)      : h  [512][16], quad-XOR swizzle, stride 16
//   xc  [12288, 16384)     : x chunk [512][8], XOR swizzle, stride 8
__global__ __launch_bounds__(THREADS, 3)
void fb_kernel(const float* __restrict__ x, const float* __restrict__ W1,
               const float* __restrict__ W2, float* __restrict__ out, int n)
{
    extern __shared__ float smem[];
    float* W1s = smem;
    float* hb  = smem + 4096;
    float* xc  = smem + 12288;

    const int t     = threadIdx.x;
    const int row0  = blockIdx.x * RTILE;
    const int nrows = min(RTILE, n - row0);

    for (int i = t; i < D * H; i += THREADS) W1s[i] = W1[i];

    // ================= pass 1: h = relu(x @ W1), 2 rows/thread ==============
    const int r1 = t, r2 = t + 256;
    const int hx1 = (r1 >> 2) & 7, hx2 = (r2 >> 2) & 7;   // xc column swizzle
    u64 acc[16];
    #pragma unroll
    for (int i = 0; i < 16; i++) acc[i] = 0ULL;

    for (int c = 0; c < NCH; c++) {
        __syncthreads();
        // stage chunk: coalesced LDG.128, XOR-swizzled scalar STS (conflict-free)
        #pragma unroll
        for (int it = 0; it < 4; it++) {
            int f4 = t + it * THREADS;          // 0..1023
            int rr = f4 >> 1, k4 = f4 & 1;
            if (rr < nrows) {
                const float4 v = *reinterpret_cast<const float4*>(
                    x + (long long)(row0 + rr) * D + c * CHUNK + 4 * k4);
                int hh = (rr >> 2) & 7;
                float* b = xc + rr * CHUNK;
                b[(4 * k4 + 0) ^ hh] = v.x;
                b[(4 * k4 + 1) ^ hh] = v.y;
                b[(4 * k4 + 2) ^ hh] = v.z;
                b[(4 * k4 + 3) ^ hh] = v.w;
            }
        }
        __syncthreads();

        const float* wrow = W1s + c * CHUNK * H;
        #pragma unroll
        for (int kk = 0; kk < CHUNK; kk++) {
            const ulonglong2* wq = reinterpret_cast<const ulonglong2*>(wrow + kk * H);
            ulonglong2 wa = wq[0], wb = wq[1];     // broadcast: 1 wavefront each
            float x1 = xc[r1 * CHUNK + (kk ^ hx1)];
            float x2 = xc[r2 * CHUNK + (kk ^ hx2)];
            u64 xx1 = pack2(x1, x1), xx2 = pack2(x2, x2);
            acc[0] = fma2(xx1, wa.x, acc[0]);
            acc[8] = fma2(xx2, wa.x, acc[8]);
            acc[1] = fma2(xx1, wa.y, acc[1]);
            acc[9] = fma2(xx2, wa.y, acc[9]);
            acc[2] = fma2(xx1, wb.x, acc[2]);
            acc[10] = fma2(xx2, wb.x, acc[10]);
            acc[3] = fma2(xx1, wb.y, acc[3]);
            acc[11] = fma2(xx2, wb.y, acc[11]);
            ulonglong2 wc = wq[2], wd = wq[3];
            acc[4] = fma2(xx1, wc.x, acc[4]);
            acc[12] = fma2(xx2, wc.x, acc[12]);
            acc[5] = fma2(xx1, wc.y, acc[5]);
            acc[13] = fma2(xx2, wc.y, acc[13]);
            acc[6] = fma2(xx1, wd.x, acc[6]);
            acc[14] = fma2(xx2, wd.x, acc[14]);
            acc[7] = fma2(xx1, wd.y, acc[7]);
            acc[15] = fma2(xx2, wd.y, acc[15]);
        }
    }

    // ---- ReLU + store h rows (STS.128, quad-XOR swizzle, conflict-free) ----
    #pragma unroll
    for (int rr = 0; rr < 2; rr++) {
        int r = (rr == 0) ? r1 : r2;
        int fr = (r >> 1) & 3;
        const u64* a = acc + rr * 8;
        #pragma unroll
        for (int q = 0; q < 4; q++) {
            float a0, a1, b0, b1;
            unpack2(a[2 * q + 0], a0, a1);
            unpack2(a[2 * q + 1], b0, b1);
            float4 v = make_float4(fmaxf(a0, 0.f), fmaxf(a1, 0.f),
                                   fmaxf(b0, 0.f), fmaxf(b1, 0.f));
            *reinterpret_cast<float4*>(hb + r * H + 4 * (q ^ fr)) = v;
        }
    }
    __syncthreads();

    // ================= pass 2: lane = k-column; W2 in registers =============
    const int w    = t >> 5, lane = t & 31;
    const int rbase = (w >> 2) * 256;            // warps 0-3: rows 0-255, 4-7: 256-511
    const int kq    = w & 3;
    const int k0    = kq * 64 + lane;
    const int k1    = k0 + 32;

    u64 w2a[8], w2b[8];                          // W2 columns k0, k1 (j-pairs)
    #pragma unroll
    for (int j = 0; j < 8; j++) {
        w2a[j] = pack2(W2[(2 * j) * D + k0], W2[(2 * j + 1) * D + k0]);
        w2b[j] = pack2(W2[(2 * j) * D + k1], W2[(2 * j + 1) * D + k1]);
    }

    const int rend = max(0, min(256, nrows - rbase));
    #pragma unroll 2
    for (int ri = 0; ri < rend; ri++) {
        int r  = rbase + ri;
        int fr = (r >> 1) & 3;
        const float* hr = hb + r * H;
        ulonglong2 q0 = *reinterpret_cast<const ulonglong2*>(hr + 4 * (0 ^ fr));
        ulonglong2 q1 = *reinterpret_cast<const ulonglong2*>(hr + 4 * (1 ^ fr));
        ulonglong2 q2 = *reinterpret_cast<const ulonglong2*>(hr + 4 * (2 ^ fr));
        ulonglong2 q3 = *reinterpret_cast<const ulonglong2*>(hr + 4 * (3 ^ fr));

        u64 sa0 = 0ULL, sa1 = 0ULL, sb0 = 0ULL, sb1 = 0ULL;
        sa0 = fma2(q0.x, w2a[0], sa0);
        sb0 = fma2(q0.x, w2b[0], sb0);
        sa1 = fma2(q0.y, w2a[1], sa1);
        sb1 = fma2(q0.y, w2b[1], sb1);
        sa0 = fma2(q1.x, w2a[2], sa0);
        sb0 = fma2(q1.x, w2b[2], sb0);
        sa1 = fma2(q1.y, w2a[3], sa1);
        sb1 = fma2(q1.y, w2b[3], sb1);
        sa0 = fma2(q2.x, w2a[4], sa0);
        sb0 = fma2(q2.x, w2b[4], sb0);
        sa1 = fma2(q2.y, w2a[5], sa1);
        sb1 = fma2(q2.y, w2b[5], sb1);
        sa0 = fma2(q3.x, w2a[6], sa0);
        sb0 = fma2(q3.x, w2b[6], sb0);
        sa1 = fma2(q3.y, w2a[7], sa1);
        sb1 = fma2(q3.y, w2b[7], sb1);

        float a0, a1, b0, b1;
        unpack2(sa0, a0, a1);
        unpack2(sa1, b0, b1);
        float s0 = (a0 + b0) + (a1 + b1);
        unpack2(sb0, a0, a1);
        unpack2(sb1, b0, b1);
        float s1 = (a0 + b0) + (a1 + b1);

        long long g = (long long)(row0 + r) * D;
        float xv0 = x[g + k0];
        float xv1 = x[g + k1];
        out[g + k0] = xv0 * sigmoid2(s0);
        out[g + k1] = xv1 * sigmoid2(s1);
    }
}

extern "C" void kernel_launch(void* const* d_in, const int* in_sizes, int n_in,
                              void* d_out, int out_size) {
    const float* x  = (const float*)d_in[0];
    const float* W1 = (const float*)d_in[1];
    const float* W2 = (const float*)d_in[2];
    float* out = (float*)d_out;
    int n = in_sizes[0] / D;

    int smem_bytes = 16384 * (int)sizeof(float);   // 64 KB
    cudaFuncSetAttribute(fb_kernel, cudaFuncAttributeMaxDynamicSharedMemorySize, smem_bytes);
    int grid = (n + RTILE - 1) / RTILE;
    fb_kernel<<<grid, THREADS, smem_bytes>>>(x, W1, W2, out, n);
}

// round 7
// speedup vs baseline: 2.6558x; 1.0872x over previous
#include <cuda_runtime.h>

#define D        256
#define H        16
#define RTILE    256    // rows per block
#define THREADS  256
#define CHUNK    16     // k-columns staged per chunk
#define NCH      16     // 256/16

typedef unsigned long long u64;

static __device__ __forceinline__ u64 pack2(float a, float b) {
    u64 r; asm("mov.b64 %0, {%1, %2};" : "=l"(r) : "f"(a), "f"(b)); return r;
}
static __device__ __forceinline__ void unpack2(u64 v, float& a, float& b) {
    asm("mov.b64 {%0, %1}, %2;" : "=f"(a), "=f"(b) : "l"(v));
}
static __device__ __forceinline__ u64 fma2(u64 a, u64 b, u64 c) {
    u64 d; asm("fma.rn.f32x2 %0, %1, %2, %3;" : "=l"(d) : "l"(a), "l"(b), "l"(c)); return d;
}
static __device__ __forceinline__ float ex2f(float x) {
    float r; asm("ex2.approx.f32 %0, %1;" : "=f"(r) : "f"(x)); return r;
}
static __device__ __forceinline__ float rcpf(float x) {
    float r; asm("rcp.approx.f32 %0, %1;" : "=f"(r) : "f"(x)); return r;
}
static __device__ __forceinline__ float sigmoid2(float s) {
    return rcpf(1.0f + ex2f(s * -2.8853900817779268f));
}
static __device__ __forceinline__ void cpa16(float* dst, const float* src) {
    unsigned s = (unsigned)__cvta_generic_to_shared(dst);
    asm volatile("cp.async.ca.shared.global [%0], [%1], 16;" :: "r"(s), "l"(src) : "memory");
}

// Shared (floats): W1s [0,4096) | xc [4096,8192) [256][16] quad-swizzled
//                  hb [8192,12288) [256][16] quad-swizzled
__global__ __launch_bounds__(THREADS, 4)
void fb_kernel(const float* __restrict__ x, const float* __restrict__ W1,
               const float* __restrict__ W2, float* __restrict__ out, int n)
{
    extern __shared__ float smem[];
    float* W1s = smem;
    float* xc  = smem + 4096;
    float* hb  = smem + 8192;

    const int t     = threadIdx.x;
    const int row0  = blockIdx.x * RTILE;
    const int nrows = min(RTILE, n - row0);

    // stage W1 (k-major, broadcast reads later)
    #pragma unroll
    for (int i = 0; i < 16; i++) W1s[t + i * THREADS] = W1[t + i * THREADS];

    // ================= pass 1: h = relu(x @ W1), 1 row/thread ===============
    const int r   = t;
    const int qs1 = (r >> 1) & 3;
    u64 acc[8];
    #pragma unroll
    for (int i = 0; i < 8; i++) acc[i] = 0ULL;

    for (int c = 0; c < NCH; c++) {
        __syncthreads();                       // xc free for reuse
        // stage chunk via cp.async: 256 rows x 16 floats, quad-swizzled
        #pragma unroll
        for (int it = 0; it < 4; it++) {
            int idx = t + it * THREADS;        // 0..1023 float4 slots
            int rr = idx >> 2, q = idx & 3;
            if (rr < nrows)
                cpa16(xc + rr * CHUNK + 4 * (q ^ ((rr >> 1) & 3)),
                      x + (long long)(row0 + rr) * D + c * CHUNK + 4 * q);
        }
        asm volatile("cp.async.commit_group;" ::: "memory");
        asm volatile("cp.async.wait_group 0;" ::: "memory");
        __syncthreads();

        const float* wbase = W1s + c * CHUNK * H;
        #pragma unroll
        for (int q = 0; q < 4; q++) {
            float4 xv = *reinterpret_cast<const float4*>(xc + r * CHUNK + 4 * (q ^ qs1));
            #pragma unroll
            for (int i = 0; i < 4; i++) {
                float xs = (i == 0) ? xv.x : (i == 1) ? xv.y : (i == 2) ? xv.z : xv.w;
                u64 xx = pack2(xs, xs);
                const ulonglong2* wq =
                    reinterpret_cast<const ulonglong2*>(wbase + (4 * q + i) * H);
                ulonglong2 wa = wq[0], wb = wq[1];
                acc[0] = fma2(xx, wa.x, acc[0]);
                acc[1] = fma2(xx, wa.y, acc[1]);
                acc[2] = fma2(xx, wb.x, acc[2]);
                acc[3] = fma2(xx, wb.y, acc[3]);
                ulonglong2 wc = wq[2], wd = wq[3];
                acc[4] = fma2(xx, wc.x, acc[4]);
                acc[5] = fma2(xx, wc.y, acc[5]);
                acc[6] = fma2(xx, wd.x, acc[6]);
                acc[7] = fma2(xx, wd.y, acc[7]);
            }
        }
    }

    // ReLU + store h row (STS.128, same quad swizzle -> conflict-free)
    #pragma unroll
    for (int q = 0; q < 4; q++) {
        float a0, a1, b0, b1;
        unpack2(acc[2 * q + 0], a0, a1);
        unpack2(acc[2 * q + 1], b0, b1);
        float4 v = make_float4(fmaxf(a0, 0.f), fmaxf(a1, 0.f),
                               fmaxf(b0, 0.f), fmaxf(b1, 0.f));
        *reinterpret_cast<float4*>(hb + r * H + 4 * (q ^ qs1)) = v;
    }
    __syncthreads();

    // ================= pass 2: lane = k-column; W2 in registers =============
    const int w = t >> 5, lane = t & 31;
    const int rbase = (w >> 2) * 128;          // warps 0-3: rows 0-127; 4-7: 128-255
    const int kq = w & 3;
    const int k0 = kq * 64 + lane;
    const int k1 = k0 + 32;

    u64 w2a[8], w2b[8];
    #pragma unroll
    for (int j = 0; j < 8; j++) {
        w2a[j] = pack2(W2[(2 * j) * D + k0], W2[(2 * j + 1) * D + k0]);
        w2b[j] = pack2(W2[(2 * j) * D + k1], W2[(2 * j + 1) * D + k1]);
    }

    const int rend = max(0, min(128, nrows - rbase));
    const long long gbase = (long long)(row0 + rbase) * D;

    float nx0 = 0.f, nx1 = 0.f;
    if (rend > 0) { nx0 = x[gbase + k0]; nx1 = x[gbase + k1]; }

    #pragma unroll 2
    for (int ri = 0; ri < rend; ri++) {
        float xv0 = nx0, xv1 = nx1;
        if (ri + 1 < rend) {
            nx0 = x[gbase + (long long)(ri + 1) * D + k0];
            nx1 = x[gbase + (long long)(ri + 1) * D + k1];
        }
        int rr = rbase + ri;
        int fq = (rr >> 1) & 3;
        const float* hr = hb + rr * H;

        u64 sa = 0ULL, sb = 0ULL;
        #pragma unroll
        for (int q = 0; q < 4; q++) {
            ulonglong2 hq = *reinterpret_cast<const ulonglong2*>(hr + 4 * (q ^ fq));
            sa = fma2(hq.x, w2a[2 * q + 0], sa);
            sb = fma2(hq.x, w2b[2 * q + 0], sb);
            sa = fma2(hq.y, w2a[2 * q + 1], sa);
            sb = fma2(hq.y, w2b[2 * q + 1], sb);
        }
        float a0, a1, b0, b1;
        unpack2(sa, a0, a1);
        float s0 = a0 + a1;
        unpack2(sb, b0, b1);
        float s1 = b0 + b1;

        long long g = gbase + (long long)ri * D;
        out[g + k0] = xv0 * sigmoid2(s0);
        out[g + k1] = xv1 * sigmoid2(s1);
    }
}

extern "C" void kernel_launch(void* const* d_in, const int* in_sizes, int n_in,
                              void* d_out, int out_size) {
    const float* x  = (const float*)d_in[0];
    const float* W1 = (const float*)d_in[1];
    const float* W2 = (const float*)d_in[2];
    float* out = (float*)d_out;
    int n = in_sizes[0] / D;

    int smem_bytes = 12288 * (int)sizeof(float);   // 48 KB -> 4 CTAs/SM
    cudaFuncSetAttribute(fb_kernel, cudaFuncAttributeMaxDynamicSharedMemorySize, smem_bytes);
    int grid = (n + RTILE - 1) / RTILE;
    fb_kernel<<<grid, THREADS, smem_bytes>>>(x, W1, W2, out, n);
}